// round 3
// baseline (speedup 1.0000x reference)
#include <cuda_runtime.h>
#include <math.h>

// ---------------- Problem constants ----------------
#define BB   128
#define LL   128
#define JJ   64
#define EE   128
#define SS   129
#define HH   2
#define HD   64
#define CATN 1000
#define ROWS (BB*SS)   // 16512

// ---------------- Device scratch ----------------
__device__ float g_x  [ROWS*EE];
__device__ float g_q  [ROWS*EE];
__device__ float g_k  [ROWS*EE];
__device__ float g_v  [ROWS*EE];
__device__ float g_o  [ROWS*EE];
__device__ float g_tmp[ROWS*EE];
__device__ float g_f1 [ROWS*EE];
__device__ float g_f2 [ROWS*EE];
__device__ float g_P  [BB*HH*SS*SS];
__device__ float g_h  [BB*EE];
__device__ float g_x1 [BB*CATN];

// ---------------- TF32 helpers ----------------
__device__ __forceinline__ unsigned f2tf(float x) {
    unsigned u;
    asm("cvt.rna.tf32.f32 %0, %1;" : "=r"(u) : "f"(x));
    return u;
}
__device__ __forceinline__ void mma_tf32(float* d, const unsigned* a, const unsigned* b) {
    asm volatile(
        "mma.sync.aligned.m16n8k8.row.col.f32.tf32.tf32.f32 "
        "{%0,%1,%2,%3}, {%4,%5,%6,%7}, {%8,%9}, {%0,%1,%2,%3};\n"
        : "+f"(d[0]), "+f"(d[1]), "+f"(d[2]), "+f"(d[3])
        : "r"(a[0]), "r"(a[1]), "r"(a[2]), "r"(a[3]), "r"(b[0]), "r"(b[1]));
}

// ---------------- TF32x3 GEMM: C = A[MxK] @ W[KxN] + bias (opt relu) ------
// Block tile 128x128, BK=16, 256 threads = 8 warps (2M x 4N), warp tile 64x32.
// A,B split into hi/lo tf32 parts; 3 MMAs per tile -> ~fp32 accuracy.
__global__ __launch_bounds__(256)
void gemm_tf32(const float* __restrict__ A, const float* __restrict__ W,
               const float* __restrict__ bias, float* __restrict__ C,
               int M, int N, int K, int relu)
{
    __shared__ float Ah[128][20];
    __shared__ float Al[128][20];
    __shared__ float Bh[16][132];
    __shared__ float Bl[16][132];

    const int bm = blockIdx.y * 128, bn = blockIdx.x * 128;
    const int tid = threadIdx.x;
    const int warp = tid >> 5, lane = tid & 31;
    const int wm = warp & 1, wn = warp >> 1;          // 2 x 4 warps
    const int g = lane >> 2, t = lane & 3;

    float acc[4][4][4];
    #pragma unroll
    for (int i = 0; i < 4; i++)
        #pragma unroll
        for (int j = 0; j < 4; j++)
            #pragma unroll
            for (int r = 0; r < 4; r++) acc[i][j][r] = 0.f;

    for (int k0 = 0; k0 < K; k0 += 16) {
        // ---- load A tile 128x16 (2 float4 per thread) ----
        {
            int r = tid >> 2, c = (tid & 3) * 4;
            #pragma unroll
            for (int it = 0; it < 2; it++) {
                int row = r + it * 64;
                int m = bm + row, k = k0 + c;
                float v0 = 0.f, v1 = 0.f, v2 = 0.f, v3 = 0.f;
                if (m < M) {
                    if (k + 3 < K) {
                        float4 v = *reinterpret_cast<const float4*>(A + (size_t)m*K + k);
                        v0 = v.x; v1 = v.y; v2 = v.z; v3 = v.w;
                    } else {
                        if (k     < K) v0 = A[(size_t)m*K + k];
                        if (k + 1 < K) v1 = A[(size_t)m*K + k + 1];
                        if (k + 2 < K) v2 = A[(size_t)m*K + k + 2];
                        if (k + 3 < K) v3 = A[(size_t)m*K + k + 3];
                    }
                }
                unsigned h0 = f2tf(v0), h1 = f2tf(v1), h2 = f2tf(v2), h3 = f2tf(v3);
                Ah[row][c]   = __uint_as_float(h0);
                Ah[row][c+1] = __uint_as_float(h1);
                Ah[row][c+2] = __uint_as_float(h2);
                Ah[row][c+3] = __uint_as_float(h3);
                Al[row][c]   = __uint_as_float(f2tf(v0 - __uint_as_float(h0)));
                Al[row][c+1] = __uint_as_float(f2tf(v1 - __uint_as_float(h1)));
                Al[row][c+2] = __uint_as_float(f2tf(v2 - __uint_as_float(h2)));
                Al[row][c+3] = __uint_as_float(f2tf(v3 - __uint_as_float(h3)));
            }
        }
        // ---- load B tile 16x128 (2 float4 per thread) ----
        {
            int rr = tid >> 5, c = (tid & 31) * 4;
            #pragma unroll
            for (int it = 0; it < 2; it++) {
                int row = rr + it * 8;
                int k = k0 + row, n = bn + c;
                float v0 = 0.f, v1 = 0.f, v2 = 0.f, v3 = 0.f;
                if (k < K) {
                    if (n + 3 < N) {
                        float4 v = *reinterpret_cast<const float4*>(W + (size_t)k*N + n);
                        v0 = v.x; v1 = v.y; v2 = v.z; v3 = v.w;
                    } else {
                        if (n     < N) v0 = W[(size_t)k*N + n];
                        if (n + 1 < N) v1 = W[(size_t)k*N + n + 1];
                        if (n + 2 < N) v2 = W[(size_t)k*N + n + 2];
                        if (n + 3 < N) v3 = W[(size_t)k*N + n + 3];
                    }
                }
                unsigned h0 = f2tf(v0), h1 = f2tf(v1), h2 = f2tf(v2), h3 = f2tf(v3);
                Bh[row][c]   = __uint_as_float(h0);
                Bh[row][c+1] = __uint_as_float(h1);
                Bh[row][c+2] = __uint_as_float(h2);
                Bh[row][c+3] = __uint_as_float(h3);
                Bl[row][c]   = __uint_as_float(f2tf(v0 - __uint_as_float(h0)));
                Bl[row][c+1] = __uint_as_float(f2tf(v1 - __uint_as_float(h1)));
                Bl[row][c+2] = __uint_as_float(f2tf(v2 - __uint_as_float(h2)));
                Bl[row][c+3] = __uint_as_float(f2tf(v3 - __uint_as_float(h3)));
            }
        }
        __syncthreads();

        #pragma unroll
        for (int kk = 0; kk < 16; kk += 8) {
            unsigned ah[4][4], al[4][4], bh[4][2], bl[4][2];
            #pragma unroll
            for (int i = 0; i < 4; i++) {
                int row = wm*64 + i*16 + g;
                ah[i][0] = __float_as_uint(Ah[row][kk + t]);
                ah[i][1] = __float_as_uint(Ah[row + 8][kk + t]);
                ah[i][2] = __float_as_uint(Ah[row][kk + t + 4]);
                ah[i][3] = __float_as_uint(Ah[row + 8][kk + t + 4]);
                al[i][0] = __float_as_uint(Al[row][kk + t]);
                al[i][1] = __float_as_uint(Al[row + 8][kk + t]);
                al[i][2] = __float_as_uint(Al[row][kk + t + 4]);
                al[i][3] = __float_as_uint(Al[row + 8][kk + t + 4]);
            }
            #pragma unroll
            for (int j = 0; j < 4; j++) {
                int col = wn*32 + j*8 + g;
                bh[j][0] = __float_as_uint(Bh[kk + t][col]);
                bh[j][1] = __float_as_uint(Bh[kk + t + 4][col]);
                bl[j][0] = __float_as_uint(Bl[kk + t][col]);
                bl[j][1] = __float_as_uint(Bl[kk + t + 4][col]);
            }
            #pragma unroll
            for (int i = 0; i < 4; i++)
                #pragma unroll
                for (int j = 0; j < 4; j++) {
                    mma_tf32(acc[i][j], ah[i], bl[j]);
                    mma_tf32(acc[i][j], al[i], bh[j]);
                    mma_tf32(acc[i][j], ah[i], bh[j]);
                }
        }
        __syncthreads();
    }

    // ---- epilogue ----
    #pragma unroll
    for (int i = 0; i < 4; i++) {
        int r0 = bm + wm*64 + i*16 + g;
        #pragma unroll
        for (int j = 0; j < 4; j++) {
            int n0 = bn + wn*32 + j*8 + 2*t;
            #pragma unroll
            for (int half = 0; half < 2; half++) {
                int r = r0 + half*8;
                if (r >= M) continue;
                float d0 = acc[i][j][half*2], d1 = acc[i][j][half*2 + 1];
                if (n0 < N) {
                    float v = d0 + bias[n0];
                    if (relu) v = fmaxf(v, 0.f);
                    C[(size_t)r*N + n0] = v;
                }
                if (n0 + 1 < N) {
                    float v = d1 + bias[n0 + 1];
                    if (relu) v = fmaxf(v, 0.f);
                    C[(size_t)r*N + n0 + 1] = v;
                }
            }
        }
    }
}

// ---------------- Embedding: warp per bag, float4 ----------------
__global__ void embed_kernel(const int* __restrict__ cat_arr,
                             const int* __restrict__ amt_arr,
                             const int* __restrict__ dt_arr,
                             const float4* __restrict__ cat4,
                             const float4* __restrict__ amt4,
                             const float4* __restrict__ dt4,
                             float4* __restrict__ x4)
{
    int tid = threadIdx.x, w = tid >> 5, lane = tid & 31;
    int bag = blockIdx.x * 4 + w;
    __shared__ int sc[4][64];
    __shared__ int sa[4][64];
    sc[w][lane]      = cat_arr[(size_t)bag*JJ + lane];
    sc[w][lane + 32] = cat_arr[(size_t)bag*JJ + lane + 32];
    sa[w][lane]      = amt_arr[(size_t)bag*JJ + lane];
    sa[w][lane + 32] = amt_arr[(size_t)bag*JJ + lane + 32];
    __syncwarp();
    float4 acc = make_float4(0.f, 0.f, 0.f, 0.f);
    #pragma unroll 4
    for (int j = 0; j < JJ; j++) {
        int c = sc[w][j];
        if (c != CATN) {
            float4 u = __ldg(&cat4[(size_t)c*32 + lane]);
            float4 v = __ldg(&amt4[(size_t)sa[w][j]*32 + lane]);
            acc.x += u.x + v.x; acc.y += u.y + v.y;
            acc.z += u.z + v.z; acc.w += u.w + v.w;
        }
    }
    float4 d = __ldg(&dt4[(size_t)dt_arr[bag]*32 + lane]);
    acc.x += d.x; acc.y += d.y; acc.z += d.z; acc.w += d.w;
    int b = bag >> 7, l = bag & 127;
    x4[((size_t)b*SS + l + 1)*32 + lane] = acc;
}

__global__ void id_kernel(const int* __restrict__ id_arr,
                          const float* __restrict__ id_tab)
{
    int b = blockIdx.x, e = threadIdx.x;
    g_x[(size_t)b*SS*EE + e] = id_tab[(size_t)id_arr[b]*EE + e];
}

// ---------------- Attention: scores + softmax (warp per query row) ----------
__global__ void attn_scores(const float* __restrict__ q,
                            const float* __restrict__ k,
                            float* __restrict__ P)
{
    int bh = blockIdx.x;
    int b = bh >> 1, h = bh & 1;
    __shared__ float sk[SS*65];
    __shared__ float sq[8][64];
    int tid = threadIdx.x;
    for (int idx = tid; idx < SS*HD; idx += 256) {
        int s = idx >> 6, d = idx & 63;
        sk[s*65 + d] = k[((size_t)b*SS + s)*EE + h*HD + d];
    }
    __syncthreads();
    int wid = tid >> 5, lane = tid & 31;
    for (int it = 0; it < 17; it++) {
        int i = it*8 + wid;
        __syncwarp();
        if (i < SS) {
            const float* qr = q + ((size_t)b*SS + i)*EE + h*HD;
            sq[wid][lane]      = qr[lane];
            sq[wid][lane + 32] = qr[lane + 32];
        }
        __syncwarp();
        if (i < SS) {
            float sc[5];
            float mx = -1e30f;
            #pragma unroll
            for (int m = 0; m < 5; m++) {
                int j = lane + m*32;
                float s = -1e30f;
                if (j < SS) {
                    s = 0.f;
                    #pragma unroll 8
                    for (int d = 0; d < HD; d++) s += sq[wid][d] * sk[j*65 + d];
                    s *= 0.125f;
                }
                sc[m] = s;
                mx = fmaxf(mx, s);
            }
            #pragma unroll
            for (int o = 16; o > 0; o >>= 1)
                mx = fmaxf(mx, __shfl_xor_sync(0xffffffffu, mx, o));
            float sum = 0.f;
            #pragma unroll
            for (int m = 0; m < 5; m++) {
                int j = lane + m*32;
                if (j < SS) { sc[m] = __expf(sc[m] - mx); sum += sc[m]; }
            }
            #pragma unroll
            for (int o = 16; o > 0; o >>= 1)
                sum += __shfl_xor_sync(0xffffffffu, sum, o);
            float inv = 1.f / sum;
            #pragma unroll
            for (int m = 0; m < 5; m++) {
                int j = lane + m*32;
                if (j < SS) P[((size_t)bh*SS + i)*SS + j] = sc[m] * inv;
            }
        }
    }
}

// ---------------- Attention: out = P @ V ----------
__global__ void attn_av(const float* __restrict__ P,
                        const float* __restrict__ v,
                        float* __restrict__ o)
{
    int bh = blockIdx.x;
    int b = bh >> 1, h = bh & 1;
    __shared__ float sv[SS*64];
    __shared__ float sp[8][132];
    int tid = threadIdx.x;
    for (int idx = tid; idx < SS*HD; idx += 256) {
        int s = idx >> 6, d = idx & 63;
        sv[idx] = v[((size_t)b*SS + s)*EE + h*HD + d];
    }
    __syncthreads();
    int wid = tid >> 5, lane = tid & 31;
    for (int it = 0; it < 17; it++) {
        int i = it*8 + wid;
        __syncwarp();
        if (i < SS) {
            #pragma unroll
            for (int m = 0; m < 5; m++) {
                int j = lane + m*32;
                if (j < SS) sp[wid][j] = P[((size_t)bh*SS + i)*SS + j];
            }
        }
        __syncwarp();
        if (i < SS) {
            float a0 = 0.f, a1 = 0.f;
            #pragma unroll 4
            for (int j = 0; j < SS; j++) {
                float p = sp[wid][j];
                a0 += p * sv[j*64 + lane];
                a1 += p * sv[j*64 + lane + 32];
            }
            float* orow = o + ((size_t)b*SS + i)*EE + h*HD;
            orow[lane]      = a0;
            orow[lane + 32] = a1;
        }
    }
}

// ---------------- LayerNorm(x + add) in place ----------------
__global__ void ln_add(float* __restrict__ x, const float* __restrict__ add,
                       const float* __restrict__ g, const float* __restrict__ bta)
{
    int r = blockIdx.x, e = threadIdx.x;
    __shared__ float red[4];
    float v = x[(size_t)r*EE + e] + add[(size_t)r*EE + e];
    float s = v;
    #pragma unroll
    for (int o = 16; o > 0; o >>= 1) s += __shfl_xor_sync(0xffffffffu, s, o);
    if ((e & 31) == 0) red[e >> 5] = s;
    __syncthreads();
    float mu = (red[0] + red[1] + red[2] + red[3]) * (1.f/128.f);
    __syncthreads();
    float d = v - mu;
    float s2 = d * d;
    #pragma unroll
    for (int o = 16; o > 0; o >>= 1) s2 += __shfl_xor_sync(0xffffffffu, s2, o);
    if ((e & 31) == 0) red[e >> 5] = s2;
    __syncthreads();
    float var = (red[0] + red[1] + red[2] + red[3]) * (1.f/128.f);
    x[(size_t)r*EE + e] = d * rsqrtf(var + 1e-5f) * g[e] + bta[e];
}

// ---------------- Mean pool ----------------
__global__ void pool_kernel(const float* __restrict__ x, float* __restrict__ h)
{
    int b = blockIdx.x, e = threadIdx.x;
    float s = 0.f;
    #pragma unroll 4
    for (int l = 1; l <= LL; l++) s += x[((size_t)b*SS + l)*EE + e];
    h[(size_t)b*EE + e] = s * (1.f/128.f);
}

// ---------------- Launch ----------------
extern "C" void kernel_launch(void* const* d_in, const int* in_sizes, int n_in,
                              void* d_out, int out_size)
{
    (void)in_sizes; (void)n_in; (void)out_size;
    const int*   cat_arr = (const int*)  d_in[0];
    const int*   dt_arr  = (const int*)  d_in[1];
    const int*   amt_arr = (const int*)  d_in[2];
    const int*   id_arr  = (const int*)  d_in[3];
    const float* id_tab  = (const float*)d_in[4];
    const float* cat_tab = (const float*)d_in[5];
    const float* amt_tab = (const float*)d_in[6];
    const float* dt_tab  = (const float*)d_in[7];
    const float* Wq = (const float*)d_in[8],  *bq = (const float*)d_in[9];
    const float* Wk = (const float*)d_in[10], *bk = (const float*)d_in[11];
    const float* Wv = (const float*)d_in[12], *bv = (const float*)d_in[13];
    const float* Wo = (const float*)d_in[14], *bo = (const float*)d_in[15];
    const float* ln1g = (const float*)d_in[16], *ln1b = (const float*)d_in[17];
    const float* W1 = (const float*)d_in[18], *b1 = (const float*)d_in[19];
    const float* W2 = (const float*)d_in[20], *b2 = (const float*)d_in[21];
    const float* ln2g = (const float*)d_in[22], *ln2b = (const float*)d_in[23];
    const float* l1W = (const float*)d_in[24], *l1b = (const float*)d_in[25];
    const float* l2W = (const float*)d_in[26], *l2b = (const float*)d_in[27];
    float* out = (float*)d_out;

    float *x, *q, *k, *v, *o, *tmp, *f1, *f2, *P, *h, *x1;
    cudaGetSymbolAddress((void**)&x,   g_x);
    cudaGetSymbolAddress((void**)&q,   g_q);
    cudaGetSymbolAddress((void**)&k,   g_k);
    cudaGetSymbolAddress((void**)&v,   g_v);
    cudaGetSymbolAddress((void**)&o,   g_o);
    cudaGetSymbolAddress((void**)&tmp, g_tmp);
    cudaGetSymbolAddress((void**)&f1,  g_f1);
    cudaGetSymbolAddress((void**)&f2,  g_f2);
    cudaGetSymbolAddress((void**)&P,   g_P);
    cudaGetSymbolAddress((void**)&h,   g_h);
    cudaGetSymbolAddress((void**)&x1,  g_x1);

    // 1. embeddings
    embed_kernel<<<BB*LL/4, 128>>>(cat_arr, amt_arr, dt_arr,
                                   (const float4*)cat_tab, (const float4*)amt_tab,
                                   (const float4*)dt_tab, (float4*)x);
    id_kernel<<<BB, EE>>>(id_arr, id_tab);

    // 2. QKV projections (tf32x3 tensor-core GEMM)
    dim3 gEE(1, ROWS/128);     // N=128 -> 1 tile, M=16512 -> 129 tiles
    gemm_tf32<<<gEE, 256>>>(x, Wq, bq, q, ROWS, EE, EE, 0);
    gemm_tf32<<<gEE, 256>>>(x, Wk, bk, k, ROWS, EE, EE, 0);
    gemm_tf32<<<gEE, 256>>>(x, Wv, bv, v, ROWS, EE, EE, 0);

    // 3. attention
    attn_scores<<<BB*HH, 256>>>(q, k, P);
    attn_av<<<BB*HH, 256>>>(P, v, o);

    // 4. out proj + residual + LN1
    gemm_tf32<<<gEE, 256>>>(o, Wo, bo, tmp, ROWS, EE, EE, 0);
    ln_add<<<ROWS, EE>>>(x, tmp, ln1g, ln1b);

    // 5. FFN + residual + LN2
    gemm_tf32<<<gEE, 256>>>(x, W1, b1, f1, ROWS, EE, EE, 1);
    gemm_tf32<<<gEE, 256>>>(f1, W2, b2, f2, ROWS, EE, EE, 0);
    ln_add<<<ROWS, EE>>>(x, f2, ln2g, ln2b);

    // 6. pool + classifier head
    pool_kernel<<<BB, EE>>>(x, h);
    dim3 gHead((CATN + 127)/128, 1);
    gemm_tf32<<<gHead, 256>>>(h,  l1W, l1b, x1,  BB, CATN, EE,   1);
    gemm_tf32<<<gHead, 256>>>(x1, l2W, l2b, out, BB, CATN, CATN, 0);
}

// round 4
// speedup vs baseline: 1.2477x; 1.2477x over previous
#include <cuda_runtime.h>
#include <math.h>

// ---------------- Problem constants ----------------
#define BB   128
#define LL   128
#define JJ   64
#define EE   128
#define SS   129
#define HH   2
#define HD   64
#define CATN 1000
#define ROWS (BB*SS)   // 16512 = 258 * 64

// ---------------- Device scratch ----------------
__device__ float g_x  [ROWS*EE];
__device__ float g_q  [ROWS*EE];
__device__ float g_k  [ROWS*EE];
__device__ float g_v  [ROWS*EE];
__device__ float g_o  [ROWS*EE];
__device__ float g_tmp[ROWS*EE];
__device__ float g_f1 [ROWS*EE];
__device__ float g_f2 [ROWS*EE];
__device__ float g_P  [BB*HH*SS*SS];
__device__ float g_h  [BB*EE];
__device__ float g_x1 [BB*CATN];

// ---------------- TF32 / cp.async helpers ----------------
__device__ __forceinline__ unsigned f2tf(float x) {
    unsigned u;
    asm("cvt.rna.tf32.f32 %0, %1;" : "=r"(u) : "f"(x));
    return u;
}
__device__ __forceinline__ void split_tf(float v, unsigned& hi, unsigned& lo) {
    hi = f2tf(v);
    lo = f2tf(v - __uint_as_float(hi));
}
__device__ __forceinline__ void mma_tf32(float* d, const unsigned* a, const unsigned* b) {
    asm volatile(
        "mma.sync.aligned.m16n8k8.row.col.f32.tf32.tf32.f32 "
        "{%0,%1,%2,%3}, {%4,%5,%6,%7}, {%8,%9}, {%0,%1,%2,%3};\n"
        : "+f"(d[0]), "+f"(d[1]), "+f"(d[2]), "+f"(d[3])
        : "r"(a[0]), "r"(a[1]), "r"(a[2]), "r"(a[3]), "r"(b[0]), "r"(b[1]));
}
__device__ __forceinline__ void cp_async16(void* smem, const void* gmem) {
    unsigned s = (unsigned)__cvta_generic_to_shared(smem);
    asm volatile("cp.async.ca.shared.global [%0], [%1], 16;\n" :: "r"(s), "l"(gmem));
}

// ---------------- TF32x3 GEMM, 64x128 tile, BK=16, double-buffered cp.async --
// Requires M%64==0, N==128 (gridDim.x==1, bn=0), K%16==0. No bounds checks.
// blockIdx.z selects among up to 3 (W,bias,C) triples (QKV batching).
__global__ __launch_bounds__(256)
void gemm_tf32(const float* __restrict__ A,
               const float* __restrict__ Wa, const float* __restrict__ Wb,
               const float* __restrict__ Wc,
               const float* __restrict__ ba, const float* __restrict__ bb,
               const float* __restrict__ bc,
               float* __restrict__ Ca, float* __restrict__ Cb, float* __restrict__ Cc,
               int N, int K, int relu)
{
    const float* W    = (blockIdx.z == 0) ? Wa : (blockIdx.z == 1) ? Wb : Wc;
    const float* bias = (blockIdx.z == 0) ? ba : (blockIdx.z == 1) ? bb : bc;
    float*       C    = (blockIdx.z == 0) ? Ca : (blockIdx.z == 1) ? Cb : Cc;

    __shared__ __align__(16) float As[2][64][20];
    __shared__ __align__(16) float Bs[2][16][136];

    const int bm = blockIdx.y * 64;
    const int tid = threadIdx.x, warp = tid >> 5, lane = tid & 31;
    const int wm = warp & 1, wn = warp >> 1;      // 2 x 4 warps, warp tile 32x32
    const int g = lane >> 2, t = lane & 3;

    const int ra = tid >> 2,  ca = (tid & 3) * 4;   // A loader: row 0..63, col {0,4,8,12}
    const int rb = tid >> 5,  cb = (tid & 31) * 4;  // B loader: rows rb, rb+8

    float acc[2][4][4] = {};

    const int niter = K >> 4;
    // prefetch iter 0
    cp_async16(&As[0][ra][ca],   A + (size_t)(bm + ra) * K + ca);
    cp_async16(&Bs[0][rb][cb],   W + (size_t)rb * N + cb);
    cp_async16(&Bs[0][rb+8][cb], W + (size_t)(rb + 8) * N + cb);
    asm volatile("cp.async.commit_group;\n");

    for (int it = 0; it < niter; it++) {
        const int cur = it & 1;
        if (it + 1 < niter) {
            const int nxt = cur ^ 1, k0 = (it + 1) << 4;
            cp_async16(&As[nxt][ra][ca],   A + (size_t)(bm + ra) * K + k0 + ca);
            cp_async16(&Bs[nxt][rb][cb],   W + (size_t)(k0 + rb) * N + cb);
            cp_async16(&Bs[nxt][rb+8][cb], W + (size_t)(k0 + rb + 8) * N + cb);
            asm volatile("cp.async.commit_group;\n");
            asm volatile("cp.async.wait_group 1;\n");
        } else {
            asm volatile("cp.async.wait_group 0;\n");
        }
        __syncthreads();

        #pragma unroll
        for (int kk = 0; kk < 16; kk += 8) {
            unsigned ah[2][4], al[2][4], bh[4][2], bl[4][2];
            #pragma unroll
            for (int i = 0; i < 2; i++) {
                int row = wm*32 + i*16 + g;
                split_tf(As[cur][row    ][kk + t    ], ah[i][0], al[i][0]);
                split_tf(As[cur][row + 8][kk + t    ], ah[i][1], al[i][1]);
                split_tf(As[cur][row    ][kk + t + 4], ah[i][2], al[i][2]);
                split_tf(As[cur][row + 8][kk + t + 4], ah[i][3], al[i][3]);
            }
            #pragma unroll
            for (int j = 0; j < 4; j++) {
                int col = wn*32 + j*8 + g;
                split_tf(Bs[cur][kk + t    ][col], bh[j][0], bl[j][0]);
                split_tf(Bs[cur][kk + t + 4][col], bh[j][1], bl[j][1]);
            }
            #pragma unroll
            for (int i = 0; i < 2; i++)
                #pragma unroll
                for (int j = 0; j < 4; j++) {
                    mma_tf32(acc[i][j], ah[i], bl[j]);
                    mma_tf32(acc[i][j], al[i], bh[j]);
                    mma_tf32(acc[i][j], ah[i], bh[j]);
                }
        }
        __syncthreads();
    }

    // epilogue (no bounds checks: M%64==0, N==128)
    #pragma unroll
    for (int i = 0; i < 2; i++) {
        #pragma unroll
        for (int half = 0; half < 2; half++) {
            int r = bm + wm*32 + i*16 + g + half*8;
            #pragma unroll
            for (int j = 0; j < 4; j++) {
                int n0 = wn*32 + j*8 + 2*t;
                float d0 = acc[i][j][half*2]     + bias[n0];
                float d1 = acc[i][j][half*2 + 1] + bias[n0 + 1];
                if (relu) { d0 = fmaxf(d0, 0.f); d1 = fmaxf(d1, 0.f); }
                C[(size_t)r*N + n0]     = d0;
                C[(size_t)r*N + n0 + 1] = d1;
            }
        }
    }
}

// ---------------- Head GEMM (small M, fp32): C = relu?(A@W + b) ------------
// Tile 8m x 128n, grid (ceil(N/128), M/8). W reads coalesced, A via smem bcast.
__global__ __launch_bounds__(128)
void head_gemm(const float* __restrict__ A, const float* __restrict__ W,
               const float* __restrict__ bias, float* __restrict__ C,
               int M, int N, int K, int relu)
{
    __shared__ __align__(16) float As[8][128];
    const int bn = blockIdx.x * 128, bm = blockIdx.y * 8;
    const int tid = threadIdx.x;
    const int n = bn + tid;
    float acc[8] = {};
    for (int k0 = 0; k0 < K; k0 += 128) {
        int kc = min(128, K - k0);
        #pragma unroll
        for (int i = 0; i < 8; i++)
            As[i][tid] = (tid < kc) ? A[(size_t)(bm + i)*K + k0 + tid] : 0.f;
        __syncthreads();
        if (n < N) {
            for (int k = 0; k < kc; k += 4) {
                float w0 = W[(size_t)(k0 + k    )*N + n];
                float w1 = W[(size_t)(k0 + k + 1)*N + n];
                float w2 = W[(size_t)(k0 + k + 2)*N + n];
                float w3 = W[(size_t)(k0 + k + 3)*N + n];
                #pragma unroll
                for (int i = 0; i < 8; i++) {
                    float4 a = *reinterpret_cast<const float4*>(&As[i][k]);
                    acc[i] += a.x*w0 + a.y*w1 + a.z*w2 + a.w*w3;
                }
            }
        }
        __syncthreads();
    }
    if (n < N) {
        #pragma unroll
        for (int i = 0; i < 8; i++) {
            float v = acc[i] + bias[n];
            if (relu) v = fmaxf(v, 0.f);
            C[(size_t)(bm + i)*N + n] = v;
        }
    }
}

// ---------------- Embedding: warp per bag, float4 ----------------
__global__ void embed_kernel(const int* __restrict__ cat_arr,
                             const int* __restrict__ amt_arr,
                             const int* __restrict__ dt_arr,
                             const float4* __restrict__ cat4,
                             const float4* __restrict__ amt4,
                             const float4* __restrict__ dt4,
                             float4* __restrict__ x4)
{
    int tid = threadIdx.x, w = tid >> 5, lane = tid & 31;
    int bag = blockIdx.x * 4 + w;
    __shared__ int sc[4][64];
    __shared__ int sa[4][64];
    sc[w][lane]      = cat_arr[(size_t)bag*JJ + lane];
    sc[w][lane + 32] = cat_arr[(size_t)bag*JJ + lane + 32];
    sa[w][lane]      = amt_arr[(size_t)bag*JJ + lane];
    sa[w][lane + 32] = amt_arr[(size_t)bag*JJ + lane + 32];
    __syncwarp();
    float4 acc = make_float4(0.f, 0.f, 0.f, 0.f);
    #pragma unroll 4
    for (int j = 0; j < JJ; j++) {
        int c = sc[w][j];
        if (c != CATN) {
            float4 u = __ldg(&cat4[(size_t)c*32 + lane]);
            float4 v = __ldg(&amt4[(size_t)sa[w][j]*32 + lane]);
            acc.x += u.x + v.x; acc.y += u.y + v.y;
            acc.z += u.z + v.z; acc.w += u.w + v.w;
        }
    }
    float4 d = __ldg(&dt4[(size_t)dt_arr[bag]*32 + lane]);
    acc.x += d.x; acc.y += d.y; acc.z += d.z; acc.w += d.w;
    int b = bag >> 7, l = bag & 127;
    x4[((size_t)b*SS + l + 1)*32 + lane] = acc;
}

__global__ void id_kernel(const int* __restrict__ id_arr,
                          const float* __restrict__ id_tab)
{
    int b = blockIdx.x, e = threadIdx.x;
    g_x[(size_t)b*SS*EE + e] = id_tab[(size_t)id_arr[b]*EE + e];
}

// ---------------- Attention: scores + softmax (warp per query row) ----------
__global__ void attn_scores(const float* __restrict__ q,
                            const float* __restrict__ k,
                            float* __restrict__ P)
{
    int bh = blockIdx.x;
    int b = bh >> 1, h = bh & 1;
    __shared__ float sk[SS*65];
    __shared__ float sq[8][64];
    int tid = threadIdx.x;
    for (int idx = tid; idx < SS*HD; idx += 256) {
        int s = idx >> 6, d = idx & 63;
        sk[s*65 + d] = k[((size_t)b*SS + s)*EE + h*HD + d];
    }
    __syncthreads();
    int wid = tid >> 5, lane = tid & 31;
    for (int it = 0; it < 17; it++) {
        int i = it*8 + wid;
        __syncwarp();
        if (i < SS) {
            const float* qr = q + ((size_t)b*SS + i)*EE + h*HD;
            sq[wid][lane]      = qr[lane];
            sq[wid][lane + 32] = qr[lane + 32];
        }
        __syncwarp();
        if (i < SS) {
            float sc[5];
            float mx = -1e30f;
            #pragma unroll
            for (int m = 0; m < 5; m++) {
                int j = lane + m*32;
                float s = -1e30f;
                if (j < SS) {
                    s = 0.f;
                    #pragma unroll 8
                    for (int d = 0; d < HD; d++) s += sq[wid][d] * sk[j*65 + d];
                    s *= 0.125f;
                }
                sc[m] = s;
                mx = fmaxf(mx, s);
            }
            #pragma unroll
            for (int o = 16; o > 0; o >>= 1)
                mx = fmaxf(mx, __shfl_xor_sync(0xffffffffu, mx, o));
            float sum = 0.f;
            #pragma unroll
            for (int m = 0; m < 5; m++) {
                int j = lane + m*32;
                if (j < SS) { sc[m] = __expf(sc[m] - mx); sum += sc[m]; }
            }
            #pragma unroll
            for (int o = 16; o > 0; o >>= 1)
                sum += __shfl_xor_sync(0xffffffffu, sum, o);
            float inv = 1.f / sum;
            #pragma unroll
            for (int m = 0; m < 5; m++) {
                int j = lane + m*32;
                if (j < SS) P[((size_t)bh*SS + i)*SS + j] = sc[m] * inv;
            }
        }
    }
}

// ---------------- Attention: out = P @ V ----------
__global__ void attn_av(const float* __restrict__ P,
                        const float* __restrict__ v,
                        float* __restrict__ o)
{
    int bh = blockIdx.x;
    int b = bh >> 1, h = bh & 1;
    __shared__ float sv[SS*64];
    __shared__ float sp[8][132];
    int tid = threadIdx.x;
    for (int idx = tid; idx < SS*HD; idx += 256) {
        int s = idx >> 6, d = idx & 63;
        sv[idx] = v[((size_t)b*SS + s)*EE + h*HD + d];
    }
    __syncthreads();
    int wid = tid >> 5, lane = tid & 31;
    for (int it = 0; it < 17; it++) {
        int i = it*8 + wid;
        __syncwarp();
        if (i < SS) {
            #pragma unroll
            for (int m = 0; m < 5; m++) {
                int j = lane + m*32;
                if (j < SS) sp[wid][j] = P[((size_t)bh*SS + i)*SS + j];
            }
        }
        __syncwarp();
        if (i < SS) {
            float a0 = 0.f, a1 = 0.f;
            #pragma unroll 4
            for (int j = 0; j < SS; j++) {
                float p = sp[wid][j];
                a0 += p * sv[j*64 + lane];
                a1 += p * sv[j*64 + lane + 32];
            }
            float* orow = o + ((size_t)b*SS + i)*EE + h*HD;
            orow[lane]      = a0;
            orow[lane + 32] = a1;
        }
    }
}

// ---------------- LayerNorm(x + add) in place ----------------
__global__ void ln_add(float* __restrict__ x, const float* __restrict__ add,
                       const float* __restrict__ g, const float* __restrict__ bta)
{
    int r = blockIdx.x, e = threadIdx.x;
    __shared__ float red[4];
    float v = x[(size_t)r*EE + e] + add[(size_t)r*EE + e];
    float s = v;
    #pragma unroll
    for (int o = 16; o > 0; o >>= 1) s += __shfl_xor_sync(0xffffffffu, s, o);
    if ((e & 31) == 0) red[e >> 5] = s;
    __syncthreads();
    float mu = (red[0] + red[1] + red[2] + red[3]) * (1.f/128.f);
    __syncthreads();
    float d = v - mu;
    float s2 = d * d;
    #pragma unroll
    for (int o = 16; o > 0; o >>= 1) s2 += __shfl_xor_sync(0xffffffffu, s2, o);
    if ((e & 31) == 0) red[e >> 5] = s2;
    __syncthreads();
    float var = (red[0] + red[1] + red[2] + red[3]) * (1.f/128.f);
    x[(size_t)r*EE + e] = d * rsqrtf(var + 1e-5f) * g[e] + bta[e];
}

// ---------------- Mean pool ----------------
__global__ void pool_kernel(const float* __restrict__ x, float* __restrict__ h)
{
    int b = blockIdx.x, e = threadIdx.x;
    float s = 0.f;
    #pragma unroll 4
    for (int l = 1; l <= LL; l++) s += x[((size_t)b*SS + l)*EE + e];
    h[(size_t)b*EE + e] = s * (1.f/128.f);
}

// ---------------- Launch ----------------
extern "C" void kernel_launch(void* const* d_in, const int* in_sizes, int n_in,
                              void* d_out, int out_size)
{
    (void)in_sizes; (void)n_in; (void)out_size;
    const int*   cat_arr = (const int*)  d_in[0];
    const int*   dt_arr  = (const int*)  d_in[1];
    const int*   amt_arr = (const int*)  d_in[2];
    const int*   id_arr  = (const int*)  d_in[3];
    const float* id_tab  = (const float*)d_in[4];
    const float* cat_tab = (const float*)d_in[5];
    const float* amt_tab = (const float*)d_in[6];
    const float* dt_tab  = (const float*)d_in[7];
    const float* Wq = (const float*)d_in[8],  *bq = (const float*)d_in[9];
    const float* Wk = (const float*)d_in[10], *bk = (const float*)d_in[11];
    const float* Wv = (const float*)d_in[12], *bv = (const float*)d_in[13];
    const float* Wo = (const float*)d_in[14], *bo = (const float*)d_in[15];
    const float* ln1g = (const float*)d_in[16], *ln1b = (const float*)d_in[17];
    const float* W1 = (const float*)d_in[18], *b1 = (const float*)d_in[19];
    const float* W2 = (const float*)d_in[20], *b2 = (const float*)d_in[21];
    const float* ln2g = (const float*)d_in[22], *ln2b = (const float*)d_in[23];
    const float* l1W = (const float*)d_in[24], *l1b = (const float*)d_in[25];
    const float* l2W = (const float*)d_in[26], *l2b = (const float*)d_in[27];
    float* out = (float*)d_out;

    float *x, *q, *k, *v, *o, *tmp, *f1, *f2, *P, *h, *x1;
    cudaGetSymbolAddress((void**)&x,   g_x);
    cudaGetSymbolAddress((void**)&q,   g_q);
    cudaGetSymbolAddress((void**)&k,   g_k);
    cudaGetSymbolAddress((void**)&v,   g_v);
    cudaGetSymbolAddress((void**)&o,   g_o);
    cudaGetSymbolAddress((void**)&tmp, g_tmp);
    cudaGetSymbolAddress((void**)&f1,  g_f1);
    cudaGetSymbolAddress((void**)&f2,  g_f2);
    cudaGetSymbolAddress((void**)&P,   g_P);
    cudaGetSymbolAddress((void**)&h,   g_h);
    cudaGetSymbolAddress((void**)&x1,  g_x1);

    // 1. embeddings
    embed_kernel<<<BB*LL/4, 128>>>(cat_arr, amt_arr, dt_arr,
                                   (const float4*)cat_tab, (const float4*)amt_tab,
                                   (const float4*)dt_tab, (float4*)x);
    id_kernel<<<BB, EE>>>(id_arr, id_tab);

    // 2. QKV: one batched launch (z = 0,1,2)
    dim3 gQKV(1, ROWS/64, 3);
    gemm_tf32<<<gQKV, 256>>>(x, Wq, Wk, Wv, bq, bk, bv, q, k, v, EE, EE, 0);

    // 3. attention
    attn_scores<<<BB*HH, 256>>>(q, k, P);
    attn_av<<<BB*HH, 256>>>(P, v, o);

    // 4. out proj + residual + LN1
    dim3 g1(1, ROWS/64, 1);
    gemm_tf32<<<g1, 256>>>(o, Wo, Wo, Wo, bo, bo, bo, tmp, tmp, tmp, EE, EE, 0);
    ln_add<<<ROWS, EE>>>(x, tmp, ln1g, ln1b);

    // 5. FFN + residual + LN2
    gemm_tf32<<<g1, 256>>>(x,  W1, W1, W1, b1, b1, b1, f1, f1, f1, EE, EE, 1);
    gemm_tf32<<<g1, 256>>>(f1, W2, W2, W2, b2, b2, b2, f2, f2, f2, EE, EE, 0);
    ln_add<<<ROWS, EE>>>(x, f2, ln2g, ln2b);

    // 6. pool + classifier head (fp32, coalesced-W small-M GEMM)
    pool_kernel<<<BB, EE>>>(x, h);
    dim3 gH1((CATN + 127)/128, BB/8);
    head_gemm<<<gH1, 128>>>(h,  l1W, l1b, x1,  BB, CATN, EE,   1);
    head_gemm<<<gH1, 128>>>(x1, l2W, l2b, out, BB, CATN, CATN, 0);
}

// round 5
// speedup vs baseline: 1.4450x; 1.1582x over previous
#include <cuda_runtime.h>
#include <math.h>

// ---------------- Problem constants ----------------
#define BB   128
#define LL   128
#define JJ   64
#define EE   128
#define SS   129
#define HH   2
#define HD   64
#define CATN 1000
#define ROWS (BB*SS)   // 16512 = 258 * 64

// fused-attention smem layout (floats)
#define SKP  68            // K row pitch
#define SVP  132           // V^T row pitch / P row pitch
#define SK_FLOATS  (132*SKP)          // 8976
#define SVT_FLOATS (64*SVP)           // 8448
#define SP_FLOATS  (8*SVP)            // 1056
#define ATTN_SMEM_BYTES ((SK_FLOATS + SVT_FLOATS + SP_FLOATS) * 4)  // 73920

// ---------------- Device scratch ----------------
__device__ float g_x  [ROWS*EE];
__device__ float g_q  [ROWS*EE];
__device__ float g_k  [ROWS*EE];
__device__ float g_v  [ROWS*EE];
__device__ float g_o  [ROWS*EE];
__device__ float g_tmp[ROWS*EE];
__device__ float g_f1 [ROWS*EE];
__device__ float g_f2 [ROWS*EE];
__device__ float g_h  [BB*EE];
__device__ float g_x1 [BB*CATN];

// ---------------- TF32 / cp.async helpers ----------------
__device__ __forceinline__ unsigned f2tf(float x) {
    unsigned u;
    asm("cvt.rna.tf32.f32 %0, %1;" : "=r"(u) : "f"(x));
    return u;
}
__device__ __forceinline__ void split_tf(float v, unsigned& hi, unsigned& lo) {
    hi = f2tf(v);
    lo = f2tf(v - __uint_as_float(hi));
}
__device__ __forceinline__ void mma_tf32(float* d, const unsigned* a, const unsigned* b) {
    asm volatile(
        "mma.sync.aligned.m16n8k8.row.col.f32.tf32.tf32.f32 "
        "{%0,%1,%2,%3}, {%4,%5,%6,%7}, {%8,%9}, {%0,%1,%2,%3};\n"
        : "+f"(d[0]), "+f"(d[1]), "+f"(d[2]), "+f"(d[3])
        : "r"(a[0]), "r"(a[1]), "r"(a[2]), "r"(a[3]), "r"(b[0]), "r"(b[1]));
}
__device__ __forceinline__ void cp_async16(void* smem, const void* gmem) {
    unsigned s = (unsigned)__cvta_generic_to_shared(smem);
    asm volatile("cp.async.ca.shared.global [%0], [%1], 16;\n" :: "r"(s), "l"(gmem));
}

// ---------------- TF32x3 GEMM, 64x128 tile, BK=16, double-buffered cp.async --
__global__ __launch_bounds__(256)
void gemm_tf32(const float* __restrict__ A,
               const float* __restrict__ Wa, const float* __restrict__ Wb,
               const float* __restrict__ Wc,
               const float* __restrict__ ba, const float* __restrict__ bb,
               const float* __restrict__ bc,
               float* __restrict__ Ca, float* __restrict__ Cb, float* __restrict__ Cc,
               int N, int K, int relu)
{
    const float* W    = (blockIdx.z == 0) ? Wa : (blockIdx.z == 1) ? Wb : Wc;
    const float* bias = (blockIdx.z == 0) ? ba : (blockIdx.z == 1) ? bb : bc;
    float*       C    = (blockIdx.z == 0) ? Ca : (blockIdx.z == 1) ? Cb : Cc;

    __shared__ __align__(16) float As[2][64][20];
    __shared__ __align__(16) float Bs[2][16][136];

    const int bm = blockIdx.y * 64;
    const int tid = threadIdx.x, warp = tid >> 5, lane = tid & 31;
    const int wm = warp & 1, wn = warp >> 1;
    const int g = lane >> 2, t = lane & 3;

    const int ra = tid >> 2,  ca = (tid & 3) * 4;
    const int rb = tid >> 5,  cb = (tid & 31) * 4;

    float acc[2][4][4] = {};

    const int niter = K >> 4;
    cp_async16(&As[0][ra][ca],   A + (size_t)(bm + ra) * K + ca);
    cp_async16(&Bs[0][rb][cb],   W + (size_t)rb * N + cb);
    cp_async16(&Bs[0][rb+8][cb], W + (size_t)(rb + 8) * N + cb);
    asm volatile("cp.async.commit_group;\n");

    for (int it = 0; it < niter; it++) {
        const int cur = it & 1;
        if (it + 1 < niter) {
            const int nxt = cur ^ 1, k0 = (it + 1) << 4;
            cp_async16(&As[nxt][ra][ca],   A + (size_t)(bm + ra) * K + k0 + ca);
            cp_async16(&Bs[nxt][rb][cb],   W + (size_t)(k0 + rb) * N + cb);
            cp_async16(&Bs[nxt][rb+8][cb], W + (size_t)(k0 + rb + 8) * N + cb);
            asm volatile("cp.async.commit_group;\n");
            asm volatile("cp.async.wait_group 1;\n");
        } else {
            asm volatile("cp.async.wait_group 0;\n");
        }
        __syncthreads();

        #pragma unroll
        for (int kk = 0; kk < 16; kk += 8) {
            unsigned ah[2][4], al[2][4], bh[4][2], bl[4][2];
            #pragma unroll
            for (int i = 0; i < 2; i++) {
                int row = wm*32 + i*16 + g;
                split_tf(As[cur][row    ][kk + t    ], ah[i][0], al[i][0]);
                split_tf(As[cur][row + 8][kk + t    ], ah[i][1], al[i][1]);
                split_tf(As[cur][row    ][kk + t + 4], ah[i][2], al[i][2]);
                split_tf(As[cur][row + 8][kk + t + 4], ah[i][3], al[i][3]);
            }
            #pragma unroll
            for (int j = 0; j < 4; j++) {
                int col = wn*32 + j*8 + g;
                split_tf(Bs[cur][kk + t    ][col], bh[j][0], bl[j][0]);
                split_tf(Bs[cur][kk + t + 4][col], bh[j][1], bl[j][1]);
            }
            #pragma unroll
            for (int i = 0; i < 2; i++)
                #pragma unroll
                for (int j = 0; j < 4; j++) {
                    mma_tf32(acc[i][j], ah[i], bl[j]);
                    mma_tf32(acc[i][j], al[i], bh[j]);
                    mma_tf32(acc[i][j], ah[i], bh[j]);
                }
        }
        __syncthreads();
    }

    #pragma unroll
    for (int i = 0; i < 2; i++) {
        #pragma unroll
        for (int half = 0; half < 2; half++) {
            int r = bm + wm*32 + i*16 + g + half*8;
            #pragma unroll
            for (int j = 0; j < 4; j++) {
                int n0 = wn*32 + j*8 + 2*t;
                float d0 = acc[i][j][half*2]     + bias[n0];
                float d1 = acc[i][j][half*2 + 1] + bias[n0 + 1];
                if (relu) { d0 = fmaxf(d0, 0.f); d1 = fmaxf(d1, 0.f); }
                C[(size_t)r*N + n0]     = d0;
                C[(size_t)r*N + n0 + 1] = d1;
            }
        }
    }
}

// ---------------- Head GEMM (small M, fp32) --------------------------------
__global__ __launch_bounds__(128)
void head_gemm(const float* __restrict__ A, const float* __restrict__ W,
               const float* __restrict__ bias, float* __restrict__ C,
               int M, int N, int K, int relu)
{
    __shared__ __align__(16) float As[8][128];
    const int bn = blockIdx.x * 128, bm = blockIdx.y * 8;
    const int tid = threadIdx.x;
    const int n = bn + tid;
    float acc[8] = {};
    for (int k0 = 0; k0 < K; k0 += 128) {
        int kc = min(128, K - k0);
        #pragma unroll
        for (int i = 0; i < 8; i++)
            As[i][tid] = (tid < kc) ? A[(size_t)(bm + i)*K + k0 + tid] : 0.f;
        __syncthreads();
        if (n < N) {
            for (int k = 0; k < kc; k += 4) {
                float w0 = W[(size_t)(k0 + k    )*N + n];
                float w1 = W[(size_t)(k0 + k + 1)*N + n];
                float w2 = W[(size_t)(k0 + k + 2)*N + n];
                float w3 = W[(size_t)(k0 + k + 3)*N + n];
                #pragma unroll
                for (int i = 0; i < 8; i++) {
                    float4 a = *reinterpret_cast<const float4*>(&As[i][k]);
                    acc[i] += a.x*w0 + a.y*w1 + a.z*w2 + a.w*w3;
                }
            }
        }
        __syncthreads();
    }
    if (n < N) {
        #pragma unroll
        for (int i = 0; i < 8; i++) {
            float v = acc[i] + bias[n];
            if (relu) v = fmaxf(v, 0.f);
            C[(size_t)(bm + i)*N + n] = v;
        }
    }
}

// ---------------- Embedding: warp per bag, float4 ----------------
__global__ void embed_kernel(const int* __restrict__ cat_arr,
                             const int* __restrict__ amt_arr,
                             const int* __restrict__ dt_arr,
                             const float4* __restrict__ cat4,
                             const float4* __restrict__ amt4,
                             const float4* __restrict__ dt4,
                             float4* __restrict__ x4)
{
    int tid = threadIdx.x, w = tid >> 5, lane = tid & 31;
    int bag = blockIdx.x * 4 + w;
    __shared__ int sc[4][64];
    __shared__ int sa[4][64];
    sc[w][lane]      = cat_arr[(size_t)bag*JJ + lane];
    sc[w][lane + 32] = cat_arr[(size_t)bag*JJ + lane + 32];
    sa[w][lane]      = amt_arr[(size_t)bag*JJ + lane];
    sa[w][lane + 32] = amt_arr[(size_t)bag*JJ + lane + 32];
    __syncwarp();
    float4 acc = make_float4(0.f, 0.f, 0.f, 0.f);
    #pragma unroll 4
    for (int j = 0; j < JJ; j++) {
        int c = sc[w][j];
        if (c != CATN) {
            float4 u = __ldg(&cat4[(size_t)c*32 + lane]);
            float4 v = __ldg(&amt4[(size_t)sa[w][j]*32 + lane]);
            acc.x += u.x + v.x; acc.y += u.y + v.y;
            acc.z += u.z + v.z; acc.w += u.w + v.w;
        }
    }
    float4 d = __ldg(&dt4[(size_t)dt_arr[bag]*32 + lane]);
    acc.x += d.x; acc.y += d.y; acc.z += d.z; acc.w += d.w;
    int b = bag >> 7, l = bag & 127;
    x4[((size_t)b*SS + l + 1)*32 + lane] = acc;
}

__global__ void id_kernel(const int* __restrict__ id_arr,
                          const float* __restrict__ id_tab)
{
    int b = blockIdx.x, e = threadIdx.x;
    g_x[(size_t)b*SS*EE + e] = id_tab[(size_t)id_arr[b]*EE + e];
}

// ---------------- Fused attention: one block per (b,h) ----------------
// smem: sk[132][68] (K rows), svT[64][132] (V transposed), sp[8][132] (P rows)
__global__ __launch_bounds__(256)
void attn_fused(const float* __restrict__ q, const float* __restrict__ k,
                const float* __restrict__ v, float* __restrict__ o)
{
    extern __shared__ float smem[];
    float* sk  = smem;                       // [132][SKP]
    float* svT = smem + SK_FLOATS;           // [64][SVP]
    float* sp  = svT + SVT_FLOATS;           // [8][SVP]

    const int bh = blockIdx.x;
    const int b = bh >> 1, h = bh & 1;
    const int tid = threadIdx.x, wid = tid >> 5, lane = tid & 31;

    // load K rows (coalesced float4)
    for (int idx = tid; idx < SS*16; idx += 256) {
        int s = idx >> 4, dc = idx & 15;
        float4 t = *reinterpret_cast<const float4*>(
            &k[((size_t)b*SS + s)*EE + h*HD + dc*4]);
        *reinterpret_cast<float4*>(&sk[s*SKP + dc*4]) = t;
    }
    // load V transposed: svT[d][j]
    for (int idx = tid; idx < SS*16; idx += 256) {
        int j = idx >> 4, dc = idx & 15;
        float4 t = *reinterpret_cast<const float4*>(
            &v[((size_t)b*SS + j)*EE + h*HD + dc*4]);
        svT[(dc*4 + 0)*SVP + j] = t.x;
        svT[(dc*4 + 1)*SVP + j] = t.y;
        svT[(dc*4 + 2)*SVP + j] = t.z;
        svT[(dc*4 + 3)*SVP + j] = t.w;
    }
    // zero pad columns j = 129..131 of svT and sp
    for (int idx = tid; idx < 64*3; idx += 256) {
        int d = idx / 3, j = SS + idx % 3;
        svT[d*SVP + j] = 0.f;
    }
    if (tid < 8*3) sp[(tid/3)*SVP + SS + tid%3] = 0.f;
    __syncthreads();

    for (int it = 0; it < 17; it++) {
        int i = it*8 + wid;
        if (i < SS) {                       // uniform per warp
            // Q row into registers (L1 broadcast across lanes)
            float4 qr[16];
            const float* qp = &q[((size_t)b*SS + i)*EE + h*HD];
            #pragma unroll
            for (int c = 0; c < 16; c++)
                qr[c] = *reinterpret_cast<const float4*>(&qp[c*4]);

            float pr[5];
            float mx = -1e30f;
            #pragma unroll
            for (int m = 0; m < 5; m++) {
                int j = lane + m*32;
                float s = -1e30f;
                if (j < SS) {
                    s = 0.f;
                    #pragma unroll
                    for (int c = 0; c < 16; c++) {
                        float4 kk = *reinterpret_cast<const float4*>(&sk[j*SKP + c*4]);
                        s += qr[c].x*kk.x + qr[c].y*kk.y + qr[c].z*kk.z + qr[c].w*kk.w;
                    }
                    s *= 0.125f;            // 1/sqrt(64)
                }
                pr[m] = s;
                mx = fmaxf(mx, s);
            }
            #pragma unroll
            for (int off = 16; off > 0; off >>= 1)
                mx = fmaxf(mx, __shfl_xor_sync(0xffffffffu, mx, off));
            float sum = 0.f;
            #pragma unroll
            for (int m = 0; m < 5; m++) {
                float e = __expf(pr[m] - mx);   // masked lanes -> exp(-huge) = 0
                pr[m] = e; sum += e;
            }
            #pragma unroll
            for (int off = 16; off > 0; off >>= 1)
                sum += __shfl_xor_sync(0xffffffffu, sum, off);
            float inv = 1.f / sum;
            #pragma unroll
            for (int m = 0; m < 5; m++) {
                int j = lane + m*32;
                if (j < SS) sp[wid*SVP + j] = pr[m] * inv;
            }
            __syncwarp();

            // P·V: lane handles d = lane and d = lane+32
            float a0 = 0.f, a1 = 0.f;
            const float* prow = &sp[wid*SVP];
            const float* v0 = &svT[(size_t)lane*SVP];
            const float* v1 = &svT[(size_t)(lane + 32)*SVP];
            #pragma unroll
            for (int j4 = 0; j4 < 33; j4++) {
                float4 p  = *reinterpret_cast<const float4*>(&prow[j4*4]);
                float4 x0 = *reinterpret_cast<const float4*>(&v0[j4*4]);
                float4 x1 = *reinterpret_cast<const float4*>(&v1[j4*4]);
                a0 += p.x*x0.x + p.y*x0.y + p.z*x0.z + p.w*x0.w;
                a1 += p.x*x1.x + p.y*x1.y + p.z*x1.z + p.w*x1.w;
            }
            float* orow = &o[((size_t)b*SS + i)*EE + h*HD];
            orow[lane]      = a0;
            orow[lane + 32] = a1;
        }
    }
}

// ---------------- LayerNorm(x + add) in place ----------------
__global__ void ln_add(float* __restrict__ x, const float* __restrict__ add,
                       const float* __restrict__ g, const float* __restrict__ bta)
{
    int r = blockIdx.x, e = threadIdx.x;
    __shared__ float red[4];
    float v = x[(size_t)r*EE + e] + add[(size_t)r*EE + e];
    float s = v;
    #pragma unroll
    for (int o = 16; o > 0; o >>= 1) s += __shfl_xor_sync(0xffffffffu, s, o);
    if ((e & 31) == 0) red[e >> 5] = s;
    __syncthreads();
    float mu = (red[0] + red[1] + red[2] + red[3]) * (1.f/128.f);
    __syncthreads();
    float d = v - mu;
    float s2 = d * d;
    #pragma unroll
    for (int o = 16; o > 0; o >>= 1) s2 += __shfl_xor_sync(0xffffffffu, s2, o);
    if ((e & 31) == 0) red[e >> 5] = s2;
    __syncthreads();
    float var = (red[0] + red[1] + red[2] + red[3]) * (1.f/128.f);
    x[(size_t)r*EE + e] = d * rsqrtf(var + 1e-5f) * g[e] + bta[e];
}

// ---------------- Mean pool ----------------
__global__ void pool_kernel(const float* __restrict__ x, float* __restrict__ h)
{
    int b = blockIdx.x, e = threadIdx.x;
    float s = 0.f;
    #pragma unroll 4
    for (int l = 1; l <= LL; l++) s += x[((size_t)b*SS + l)*EE + e];
    h[(size_t)b*EE + e] = s * (1.f/128.f);
}

// ---------------- Launch ----------------
extern "C" void kernel_launch(void* const* d_in, const int* in_sizes, int n_in,
                              void* d_out, int out_size)
{
    (void)in_sizes; (void)n_in; (void)out_size;
    const int*   cat_arr = (const int*)  d_in[0];
    const int*   dt_arr  = (const int*)  d_in[1];
    const int*   amt_arr = (const int*)  d_in[2];
    const int*   id_arr  = (const int*)  d_in[3];
    const float* id_tab  = (const float*)d_in[4];
    const float* cat_tab = (const float*)d_in[5];
    const float* amt_tab = (const float*)d_in[6];
    const float* dt_tab  = (const float*)d_in[7];
    const float* Wq = (const float*)d_in[8],  *bq = (const float*)d_in[9];
    const float* Wk = (const float*)d_in[10], *bk = (const float*)d_in[11];
    const float* Wv = (const float*)d_in[12], *bv = (const float*)d_in[13];
    const float* Wo = (const float*)d_in[14], *bo = (const float*)d_in[15];
    const float* ln1g = (const float*)d_in[16], *ln1b = (const float*)d_in[17];
    const float* W1 = (const float*)d_in[18], *b1 = (const float*)d_in[19];
    const float* W2 = (const float*)d_in[20], *b2 = (const float*)d_in[21];
    const float* ln2g = (const float*)d_in[22], *ln2b = (const float*)d_in[23];
    const float* l1W = (const float*)d_in[24], *l1b = (const float*)d_in[25];
    const float* l2W = (const float*)d_in[26], *l2b = (const float*)d_in[27];
    float* out = (float*)d_out;

    float *x, *q, *k, *v, *o, *tmp, *f1, *f2, *h, *x1;
    cudaGetSymbolAddress((void**)&x,   g_x);
    cudaGetSymbolAddress((void**)&q,   g_q);
    cudaGetSymbolAddress((void**)&k,   g_k);
    cudaGetSymbolAddress((void**)&v,   g_v);
    cudaGetSymbolAddress((void**)&o,   g_o);
    cudaGetSymbolAddress((void**)&tmp, g_tmp);
    cudaGetSymbolAddress((void**)&f1,  g_f1);
    cudaGetSymbolAddress((void**)&f2,  g_f2);
    cudaGetSymbolAddress((void**)&h,   g_h);
    cudaGetSymbolAddress((void**)&x1,  g_x1);

    static int attn_smem_set = 0;
    if (!attn_smem_set) {
        cudaFuncSetAttribute(attn_fused,
                             cudaFuncAttributeMaxDynamicSharedMemorySize,
                             ATTN_SMEM_BYTES);
        attn_smem_set = 1;
    }

    // 1. embeddings
    embed_kernel<<<BB*LL/4, 128>>>(cat_arr, amt_arr, dt_arr,
                                   (const float4*)cat_tab, (const float4*)amt_tab,
                                   (const float4*)dt_tab, (float4*)x);
    id_kernel<<<BB, EE>>>(id_arr, id_tab);

    // 2. QKV: one batched launch (z = 0,1,2)
    dim3 gQKV(1, ROWS/64, 3);
    gemm_tf32<<<gQKV, 256>>>(x, Wq, Wk, Wv, bq, bk, bv, q, k, v, EE, EE, 0);

    // 3. fused attention
    attn_fused<<<BB*HH, 256, ATTN_SMEM_BYTES>>>(q, k, v, o);

    // 4. out proj + residual + LN1
    dim3 g1(1, ROWS/64, 1);
    gemm_tf32<<<g1, 256>>>(o, Wo, Wo, Wo, bo, bo, bo, tmp, tmp, tmp, EE, EE, 0);
    ln_add<<<ROWS, EE>>>(x, tmp, ln1g, ln1b);

    // 5. FFN + residual + LN2
    gemm_tf32<<<g1, 256>>>(x,  W1, W1, W1, b1, b1, b1, f1, f1, f1, EE, EE, 1);
    gemm_tf32<<<g1, 256>>>(f1, W2, W2, W2, b2, b2, b2, f2, f2, f2, EE, EE, 0);
    ln_add<<<ROWS, EE>>>(x, f2, ln2g, ln2b);

    // 6. pool + classifier head
    pool_kernel<<<BB, EE>>>(x, h);
    dim3 gH1((CATN + 127)/128, BB/8);
    head_gemm<<<gH1, 128>>>(h,  l1W, l1b, x1,  BB, CATN, EE,   1);
    head_gemm<<<gH1, 128>>>(x1, l2W, l2b, out, BB, CATN, CATN, 0);
}

// round 8
// speedup vs baseline: 1.4885x; 1.0301x over previous
#include <cuda_runtime.h>
#include <math.h>

// ---------------- Problem constants ----------------
#define BB   128
#define LL   128
#define JJ   64
#define EE   128
#define SS   129
#define HH   2
#define HD   64
#define CATN 1000
#define ROWS (BB*SS)   // 16512 = 258 * 64

// ---------------- fused mma-attention geometry ----------------
#define MCH    48            // query rows per block chunk (3 m16 tiles)
#define NCHUNK 3             // 3*48 = 144 >= 129
#define SPN    136           // padded key dim (17 n8 tiles)
#define SSP    140           // sS pitch (conflict-free A-frag reads)
#define KTP    136           // sKT pitch
#define VP     72            // sV pitch
#define QP     68            // sQ pitch
#define SS_FLOATS   (MCH*SSP)        // 6720
#define SKT_FLOATS  (64*KTP)         // 8704
#define SUN_FLOATS  (SPN*VP)         // 9792 (union: sQ 48*68=3264 fits)
#define ATTN_SMEM_BYTES ((SS_FLOATS + SKT_FLOATS + SUN_FLOATS) * 4)  // 100864

// ---------------- Device scratch ----------------
__device__ float g_x  [ROWS*EE];
__device__ float g_q  [ROWS*EE];
__device__ float g_k  [ROWS*EE];
__device__ float g_v  [ROWS*EE];
__device__ float g_o  [ROWS*EE];
__device__ float g_tmp[ROWS*EE];
__device__ float g_f1 [ROWS*EE];
__device__ float g_f2 [ROWS*EE];
__device__ float g_h  [BB*EE];
__device__ float g_x1 [BB*CATN];

// ---------------- TF32 / cp.async helpers ----------------
__device__ __forceinline__ unsigned f2tf(float x) {
    unsigned u;
    asm("cvt.rna.tf32.f32 %0, %1;" : "=r"(u) : "f"(x));
    return u;
}
__device__ __forceinline__ void split_tf(float v, unsigned& hi, unsigned& lo) {
    hi = f2tf(v);
    lo = f2tf(v - __uint_as_float(hi));
}
__device__ __forceinline__ void mma_tf32(float* d, const unsigned* a, const unsigned* b) {
    asm volatile(
        "mma.sync.aligned.m16n8k8.row.col.f32.tf32.tf32.f32 "
        "{%0,%1,%2,%3}, {%4,%5,%6,%7}, {%8,%9}, {%0,%1,%2,%3};\n"
        : "+f"(d[0]), "+f"(d[1]), "+f"(d[2]), "+f"(d[3])
        : "r"(a[0]), "r"(a[1]), "r"(a[2]), "r"(a[3]), "r"(b[0]), "r"(b[1]));
}
__device__ __forceinline__ void cp_async16(void* smem, const void* gmem) {
    unsigned s = (unsigned)__cvta_generic_to_shared(smem);
    asm volatile("cp.async.ca.shared.global [%0], [%1], 16;\n" :: "r"(s), "l"(gmem));
}

// ---------------- TF32x3 GEMM, 64x128 tile, BK=16, double-buffered cp.async --
__global__ __launch_bounds__(256)
void gemm_tf32(const float* __restrict__ A,
               const float* __restrict__ Wa, const float* __restrict__ Wb,
               const float* __restrict__ Wc,
               const float* __restrict__ ba, const float* __restrict__ bb,
               const float* __restrict__ bc,
               float* __restrict__ Ca, float* __restrict__ Cb, float* __restrict__ Cc,
               int N, int K, int relu)
{
    const float* W    = (blockIdx.z == 0) ? Wa : (blockIdx.z == 1) ? Wb : Wc;
    const float* bias = (blockIdx.z == 0) ? ba : (blockIdx.z == 1) ? bb : bc;
    float*       C    = (blockIdx.z == 0) ? Ca : (blockIdx.z == 1) ? Cb : Cc;

    __shared__ __align__(16) float As[2][64][20];
    __shared__ __align__(16) float Bs[2][16][136];

    const int bm = blockIdx.y * 64;
    const int tid = threadIdx.x, warp = tid >> 5, lane = tid & 31;
    const int wm = warp & 1, wn = warp >> 1;
    const int g = lane >> 2, t = lane & 3;

    const int ra = tid >> 2,  ca = (tid & 3) * 4;
    const int rb = tid >> 5,  cb = (tid & 31) * 4;

    float acc[2][4][4] = {};

    const int niter = K >> 4;
    cp_async16(&As[0][ra][ca],   A + (size_t)(bm + ra) * K + ca);
    cp_async16(&Bs[0][rb][cb],   W + (size_t)rb * N + cb);
    cp_async16(&Bs[0][rb+8][cb], W + (size_t)(rb + 8) * N + cb);
    asm volatile("cp.async.commit_group;\n");

    for (int it = 0; it < niter; it++) {
        const int cur = it & 1;
        if (it + 1 < niter) {
            const int nxt = cur ^ 1, k0 = (it + 1) << 4;
            cp_async16(&As[nxt][ra][ca],   A + (size_t)(bm + ra) * K + k0 + ca);
            cp_async16(&Bs[nxt][rb][cb],   W + (size_t)(k0 + rb) * N + cb);
            cp_async16(&Bs[nxt][rb+8][cb], W + (size_t)(k0 + rb + 8) * N + cb);
            asm volatile("cp.async.commit_group;\n");
            asm volatile("cp.async.wait_group 1;\n");
        } else {
            asm volatile("cp.async.wait_group 0;\n");
        }
        __syncthreads();

        #pragma unroll
        for (int kk = 0; kk < 16; kk += 8) {
            unsigned ah[2][4], al[2][4], bh[4][2], bl[4][2];
            #pragma unroll
            for (int i = 0; i < 2; i++) {
                int row = wm*32 + i*16 + g;
                split_tf(As[cur][row    ][kk + t    ], ah[i][0], al[i][0]);
                split_tf(As[cur][row + 8][kk + t    ], ah[i][1], al[i][1]);
                split_tf(As[cur][row    ][kk + t + 4], ah[i][2], al[i][2]);
                split_tf(As[cur][row + 8][kk + t + 4], ah[i][3], al[i][3]);
            }
            #pragma unroll
            for (int j = 0; j < 4; j++) {
                int col = wn*32 + j*8 + g;
                split_tf(Bs[cur][kk + t    ][col], bh[j][0], bl[j][0]);
                split_tf(Bs[cur][kk + t + 4][col], bh[j][1], bl[j][1]);
            }
            #pragma unroll
            for (int i = 0; i < 2; i++)
                #pragma unroll
                for (int j = 0; j < 4; j++) {
                    mma_tf32(acc[i][j], ah[i], bl[j]);
                    mma_tf32(acc[i][j], al[i], bh[j]);
                    mma_tf32(acc[i][j], ah[i], bh[j]);
                }
        }
        __syncthreads();
    }

    #pragma unroll
    for (int i = 0; i < 2; i++) {
        #pragma unroll
        for (int half = 0; half < 2; half++) {
            int r = bm + wm*32 + i*16 + g + half*8;
            #pragma unroll
            for (int j = 0; j < 4; j++) {
                int n0 = wn*32 + j*8 + 2*t;
                float d0 = acc[i][j][half*2]     + bias[n0];
                float d1 = acc[i][j][half*2 + 1] + bias[n0 + 1];
                if (relu) { d0 = fmaxf(d0, 0.f); d1 = fmaxf(d1, 0.f); }
                C[(size_t)r*N + n0]     = d0;
                C[(size_t)r*N + n0 + 1] = d1;
            }
        }
    }
}

// ---------------- Head GEMM (small M, fp32) --------------------------------
__global__ __launch_bounds__(128)
void head_gemm(const float* __restrict__ A, const float* __restrict__ W,
               const float* __restrict__ bias, float* __restrict__ C,
               int M, int N, int K, int relu)
{
    __shared__ __align__(16) float As[8][128];
    const int bn = blockIdx.x * 128, bm = blockIdx.y * 8;
    const int tid = threadIdx.x;
    const int n = bn + tid;
    float acc[8] = {};
    for (int k0 = 0; k0 < K; k0 += 128) {
        int kc = min(128, K - k0);
        #pragma unroll
        for (int i = 0; i < 8; i++)
            As[i][tid] = (tid < kc) ? A[(size_t)(bm + i)*K + k0 + tid] : 0.f;
        __syncthreads();
        if (n < N) {
            for (int k = 0; k < kc; k += 4) {
                float w0 = W[(size_t)(k0 + k    )*N + n];
                float w1 = W[(size_t)(k0 + k + 1)*N + n];
                float w2 = W[(size_t)(k0 + k + 2)*N + n];
                float w3 = W[(size_t)(k0 + k + 3)*N + n];
                #pragma unroll
                for (int i = 0; i < 8; i++) {
                    float4 a = *reinterpret_cast<const float4*>(&As[i][k]);
                    acc[i] += a.x*w0 + a.y*w1 + a.z*w2 + a.w*w3;
                }
            }
        }
        __syncthreads();
    }
    if (n < N) {
        #pragma unroll
        for (int i = 0; i < 8; i++) {
            float v = acc[i] + bias[n];
            if (relu) v = fmaxf(v, 0.f);
            C[(size_t)(bm + i)*N + n] = v;
        }
    }
}

// ---------------- Embedding: warp per bag, float4 ----------------
__global__ void embed_kernel(const int* __restrict__ cat_arr,
                             const int* __restrict__ amt_arr,
                             const int* __restrict__ dt_arr,
                             const float4* __restrict__ cat4,
                             const float4* __restrict__ amt4,
                             const float4* __restrict__ dt4,
                             float4* __restrict__ x4)
{
    int tid = threadIdx.x, w = tid >> 5, lane = tid & 31;
    int bag = blockIdx.x * 4 + w;
    __shared__ int sc[4][64];
    __shared__ int sa[4][64];
    sc[w][lane]      = cat_arr[(size_t)bag*JJ + lane];
    sc[w][lane + 32] = cat_arr[(size_t)bag*JJ + lane + 32];
    sa[w][lane]      = amt_arr[(size_t)bag*JJ + lane];
    sa[w][lane + 32] = amt_arr[(size_t)bag*JJ + lane + 32];
    __syncwarp();
    float4 acc = make_float4(0.f, 0.f, 0.f, 0.f);
    #pragma unroll 4
    for (int j = 0; j < JJ; j++) {
        int c = sc[w][j];
        if (c != CATN) {
            float4 u = __ldg(&cat4[(size_t)c*32 + lane]);
            float4 v = __ldg(&amt4[(size_t)sa[w][j]*32 + lane]);
            acc.x += u.x + v.x; acc.y += u.y + v.y;
            acc.z += u.z + v.z; acc.w += u.w + v.w;
        }
    }
    float4 d = __ldg(&dt4[(size_t)dt_arr[bag]*32 + lane]);
    acc.x += d.x; acc.y += d.y; acc.z += d.z; acc.w += d.w;
    int b = bag >> 7, l = bag & 127;
    x4[((size_t)b*SS + l + 1)*32 + lane] = acc;
}

__global__ void id_kernel(const int* __restrict__ id_arr,
                          const float* __restrict__ id_tab)
{
    int b = blockIdx.x, e = threadIdx.x;
    g_x[(size_t)b*SS*EE + e] = id_tab[(size_t)id_arr[b]*EE + e];
}

// ---------------- Fused tensor-core attention ----------------
// grid.x = BB*HH*NCHUNK; block = 256. Per block: 48 query rows of one (b,h).
// smem: sS[48][140] scores/P | sKT[64][136] K^T | union{ sQ[48][68], sV[136][72] }
__global__ __launch_bounds__(256)
void attn_mma(const float* __restrict__ q, const float* __restrict__ k,
              const float* __restrict__ v, float* __restrict__ o)
{
    extern __shared__ float smem[];
    float* sS  = smem;                          // [MCH][SSP]
    float* sKT = smem + SS_FLOATS;              // [64][KTP]
    float* sU  = sKT + SKT_FLOATS;              // union region

    const int blk = blockIdx.x;
    const int chunk = blk % NCHUNK;
    const int bh = blk / NCHUNK;
    const int b = bh >> 1, h = bh & 1;
    const int row0 = chunk * MCH;

    const int tid = threadIdx.x, wid = tid >> 5, lane = tid & 31;
    const int g = lane >> 2, t = lane & 3;

    // ---- load sQ (union): 48 rows x 64 ----
    {
        float* sQ = sU;   // pitch QP
        for (int idx = tid; idx < MCH*16; idx += 256) {
            int r = idx >> 4, dc = (idx & 15) * 4;
            int i = row0 + r;
            float4 tq = make_float4(0.f, 0.f, 0.f, 0.f);
            if (i < SS)
                tq = *reinterpret_cast<const float4*>(&q[((size_t)b*SS + i)*EE + h*HD + dc]);
            sQ[r*QP + dc    ] = tq.x;
            sQ[r*QP + dc + 1] = tq.y;
            sQ[r*QP + dc + 2] = tq.z;
            sQ[r*QP + dc + 3] = tq.w;
        }
    }
    // ---- load sKT[d][j] = K[j][d]; zero-pad j in [129,136) ----
    for (int idx = tid; idx < SS*16; idx += 256) {
        int j = idx >> 4, dc = (idx & 15) * 4;
        float4 tk = *reinterpret_cast<const float4*>(&k[((size_t)b*SS + j)*EE + h*HD + dc]);
        sKT[(dc    )*KTP + j] = tk.x;
        sKT[(dc + 1)*KTP + j] = tk.y;
        sKT[(dc + 2)*KTP + j] = tk.z;
        sKT[(dc + 3)*KTP + j] = tk.w;
    }
    for (int idx = tid; idx < 64*(SPN - SS); idx += 256) {
        int d = idx / (SPN - SS), j = SS + idx % (SPN - SS);
        sKT[d*KTP + j] = 0.f;
    }
    __syncthreads();

    // ---- Phase 1: scores = Q @ K^T (tf32x3), scale 0.125, into sS ----
    {
        const float* sQ = sU;
        for (int tile = wid; tile < 3*17; tile += 8) {
            int tm = tile / 17, tn = tile % 17;
            float acc[4] = {0.f, 0.f, 0.f, 0.f};
            #pragma unroll
            for (int ks = 0; ks < 8; ks++) {
                int kk = ks * 8;
                unsigned ah[4], al[4], bh2[2], bl2[2];
                int r0 = tm*16 + g;
                split_tf(sQ[(r0    )*QP + kk + t    ], ah[0], al[0]);
                split_tf(sQ[(r0 + 8)*QP + kk + t    ], ah[1], al[1]);
                split_tf(sQ[(r0    )*QP + kk + t + 4], ah[2], al[2]);
                split_tf(sQ[(r0 + 8)*QP + kk + t + 4], ah[3], al[3]);
                int col = tn*8 + g;
                split_tf(sKT[(kk + t    )*KTP + col], bh2[0], bl2[0]);
                split_tf(sKT[(kk + t + 4)*KTP + col], bh2[1], bl2[1]);
                mma_tf32(acc, ah, bl2);
                mma_tf32(acc, al, bh2);
                mma_tf32(acc, ah, bh2);
            }
            int r0 = tm*16 + g, c0 = tn*8 + 2*t;
            sS[(r0    )*SSP + c0    ] = acc[0] * 0.125f;
            sS[(r0    )*SSP + c0 + 1] = acc[1] * 0.125f;
            sS[(r0 + 8)*SSP + c0    ] = acc[2] * 0.125f;
            sS[(r0 + 8)*SSP + c0 + 1] = acc[3] * 0.125f;
        }
    }
    __syncthreads();

    // ---- Phase 2: softmax rows (warp per row), zero padded cols ----
    for (int r = wid; r < MCH; r += 8) {
        int i = row0 + r;
        if (i >= SS) continue;
        float pr[5];
        float mx = -1e30f;
        #pragma unroll
        for (int m = 0; m < 5; m++) {
            int j = lane + m*32;
            float s = (j < SS) ? sS[r*SSP + j] : -1e30f;
            pr[m] = s;
            mx = fmaxf(mx, s);
        }
        #pragma unroll
        for (int off = 16; off > 0; off >>= 1)
            mx = fmaxf(mx, __shfl_xor_sync(0xffffffffu, mx, off));
        float sum = 0.f;
        #pragma unroll
        for (int m = 0; m < 5; m++) {
            int j = lane + m*32;
            float e = (j < SS) ? __expf(pr[m] - mx) : 0.f;
            pr[m] = e; sum += e;
        }
        #pragma unroll
        for (int off = 16; off > 0; off >>= 1)
            sum += __shfl_xor_sync(0xffffffffu, sum, off);
        float inv = 1.f / sum;
        #pragma unroll
        for (int m = 0; m < 5; m++) {
            int j = lane + m*32;
            if (j < SPN) sS[r*SSP + j] = pr[m] * inv;
        }
    }
    __syncthreads();

    // ---- load sV (union, overwrites sQ): V rows, zero-pad rows >= 129 ----
    {
        float* sV = sU;   // pitch VP
        for (int idx = tid; idx < SPN*16; idx += 256) {
            int j = idx >> 4, dc = (idx & 15) * 4;
            float4 tv = make_float4(0.f, 0.f, 0.f, 0.f);
            if (j < SS)
                tv = *reinterpret_cast<const float4*>(&v[((size_t)b*SS + j)*EE + h*HD + dc]);
            sV[j*VP + dc    ] = tv.x;
            sV[j*VP + dc + 1] = tv.y;
            sV[j*VP + dc + 2] = tv.z;
            sV[j*VP + dc + 3] = tv.w;
        }
    }
    __syncthreads();

    // ---- Phase 3: out = P @ V (tf32x3), write to global ----
    {
        const float* sV = sU;
        for (int tile = wid; tile < 3*8; tile += 8) {
            int tm = tile / 8, tn = tile % 8;
            float acc[4] = {0.f, 0.f, 0.f, 0.f};
            for (int ks = 0; ks < 17; ks++) {
                int kk = ks * 8;
                unsigned ah[4], al[4], bh2[2], bl2[2];
                int r0 = tm*16 + g;
                split_tf(sS[(r0    )*SSP + kk + t    ], ah[0], al[0]);
                split_tf(sS[(r0 + 8)*SSP + kk + t    ], ah[1], al[1]);
                split_tf(sS[(r0    )*SSP + kk + t + 4], ah[2], al[2]);
                split_tf(sS[(r0 + 8)*SSP + kk + t + 4], ah[3], al[3]);
                int col = tn*8 + g;
                split_tf(sV[(kk + t    )*VP + col], bh2[0], bl2[0]);
                split_tf(sV[(kk + t + 4)*VP + col], bh2[1], bl2[1]);
                mma_tf32(acc, ah, bl2);
                mma_tf32(acc, al, bh2);
                mma_tf32(acc, ah, bh2);
            }
            int c0 = tn*8 + 2*t;
            int i0 = row0 + tm*16 + g;
            if (i0 < SS) {
                float* orow = &o[((size_t)b*SS + i0)*EE + h*HD];
                orow[c0] = acc[0]; orow[c0 + 1] = acc[1];
            }
            if (i0 + 8 < SS) {
                float* orow = &o[((size_t)b*SS + i0 + 8)*EE + h*HD];
                orow[c0] = acc[2]; orow[c0 + 1] = acc[3];
            }
        }
    }
}

// ---------------- LayerNorm(x + add) in place ----------------
__global__ void ln_add(float* __restrict__ x, const float* __restrict__ add,
                       const float* __restrict__ g, const float* __restrict__ bta)
{
    int r = blockIdx.x, e = threadIdx.x;
    __shared__ float red[4];
    float v = x[(size_t)r*EE + e] + add[(size_t)r*EE + e];
    float s = v;
    #pragma unroll
    for (int o = 16; o > 0; o >>= 1) s += __shfl_xor_sync(0xffffffffu, s, o);
    if ((e & 31) == 0) red[e >> 5] = s;
    __syncthreads();
    float mu = (red[0] + red[1] + red[2] + red[3]) * (1.f/128.f);
    __syncthreads();
    float d = v - mu;
    float s2 = d * d;
    #pragma unroll
    for (int o = 16; o > 0; o >>= 1) s2 += __shfl_xor_sync(0xffffffffu, s2, o);
    if ((e & 31) == 0) red[e >> 5] = s2;
    __syncthreads();
    float var = (red[0] + red[1] + red[2] + red[3]) * (1.f/128.f);
    x[(size_t)r*EE + e] = d * rsqrtf(var + 1e-5f) * g[e] + bta[e];
}

// ---------------- Mean pool ----------------
__global__ void pool_kernel(const float* __restrict__ x, float* __restrict__ h)
{
    int b = blockIdx.x, e = threadIdx.x;
    float s = 0.f;
    #pragma unroll 4
    for (int l = 1; l <= LL; l++) s += x[((size_t)b*SS + l)*EE + e];
    h[(size_t)b*EE + e] = s * (1.f/128.f);
}

// ---------------- Launch ----------------
extern "C" void kernel_launch(void* const* d_in, const int* in_sizes, int n_in,
                              void* d_out, int out_size)
{
    (void)in_sizes; (void)n_in; (void)out_size;
    const int*   cat_arr = (const int*)  d_in[0];
    const int*   dt_arr  = (const int*)  d_in[1];
    const int*   amt_arr = (const int*)  d_in[2];
    const int*   id_arr  = (const int*)  d_in[3];
    const float* id_tab  = (const float*)d_in[4];
    const float* cat_tab = (const float*)d_in[5];
    const float* amt_tab = (const float*)d_in[6];
    const float* dt_tab  = (const float*)d_in[7];
    const float* Wq = (const float*)d_in[8],  *bq = (const float*)d_in[9];
    const float* Wk = (const float*)d_in[10], *bk = (const float*)d_in[11];
    const float* Wv = (const float*)d_in[12], *bv = (const float*)d_in[13];
    const float* Wo = (const float*)d_in[14], *bo = (const float*)d_in[15];
    const float* ln1g = (const float*)d_in[16], *ln1b = (const float*)d_in[17];
    const float* W1 = (const float*)d_in[18], *b1 = (const float*)d_in[19];
    const float* W2 = (const float*)d_in[20], *b2 = (const float*)d_in[21];
    const float* ln2g = (const float*)d_in[22], *ln2b = (const float*)d_in[23];
    const float* l1W = (const float*)d_in[24], *l1b = (const float*)d_in[25];
    const float* l2W = (const float*)d_in[26], *l2b = (const float*)d_in[27];
    float* out = (float*)d_out;

    float *x, *q, *k, *v, *o, *tmp, *f1, *f2, *h, *x1;
    cudaGetSymbolAddress((void**)&x,   g_x);
    cudaGetSymbolAddress((void**)&q,   g_q);
    cudaGetSymbolAddress((void**)&k,   g_k);
    cudaGetSymbolAddress((void**)&v,   g_v);
    cudaGetSymbolAddress((void**)&o,   g_o);
    cudaGetSymbolAddress((void**)&tmp, g_tmp);
    cudaGetSymbolAddress((void**)&f1,  g_f1);
    cudaGetSymbolAddress((void**)&f2,  g_f2);
    cudaGetSymbolAddress((void**)&h,   g_h);
    cudaGetSymbolAddress((void**)&x1,  g_x1);

    static int attn_smem_set = 0;
    if (!attn_smem_set) {
        cudaFuncSetAttribute(attn_mma,
                             cudaFuncAttributeMaxDynamicSharedMemorySize,
                             ATTN_SMEM_BYTES);
        attn_smem_set = 1;
    }

    // 1. embeddings
    embed_kernel<<<BB*LL/4, 128>>>(cat_arr, amt_arr, dt_arr,
                                   (const float4*)cat_tab, (const float4*)amt_tab,
                                   (const float4*)dt_tab, (float4*)x);
    id_kernel<<<BB, EE>>>(id_arr, id_tab);

    // 2. QKV: one batched launch (z = 0,1,2)
    dim3 gQKV(1, ROWS/64, 3);
    gemm_tf32<<<gQKV, 256>>>(x, Wq, Wk, Wv, bq, bk, bv, q, k, v, EE, EE, 0);

    // 3. fused tensor-core attention
    attn_mma<<<BB*HH*NCHUNK, 256, ATTN_SMEM_BYTES>>>(q, k, v, o);

    // 4. out proj + residual + LN1
    dim3 g1(1, ROWS/64, 1);
    gemm_tf32<<<g1, 256>>>(o, Wo, Wo, Wo, bo, bo, bo, tmp, tmp, tmp, EE, EE, 0);
    ln_add<<<ROWS, EE>>>(x, tmp, ln1g, ln1b);

    // 5. FFN + residual + LN2
    gemm_tf32<<<g1, 256>>>(x,  W1, W1, W1, b1, b1, b1, f1, f1, f1, EE, EE, 1);
    gemm_tf32<<<g1, 256>>>(f1, W2, W2, W2, b2, b2, b2, f2, f2, f2, EE, EE, 0);
    ln_add<<<ROWS, EE>>>(x, f2, ln2g, ln2b);

    // 6. pool + classifier head
    pool_kernel<<<BB, EE>>>(x, h);
    dim3 gH1((CATN + 127)/128, BB/8);
    head_gemm<<<gH1, 128>>>(h,  l1W, l1b, x1,  BB, CATN, EE,   1);
    head_gemm<<<gH1, 128>>>(x1, l2W, l2b, out, BB, CATN, CATN, 0);
}